// round 2
// baseline (speedup 1.0000x reference)
#include <cuda_runtime.h>
#include <cuda_bf16.h>
#include <math.h>

#define Bb 8
#define Rr 1024
#define Dm 256
#define Hh 8
#define Ll 2
#define Ee 32768
#define FFd 1024
#define HDd 32
#define NEG -1000000000.0f

// ---------------- scratch (device globals; no allocation allowed) -----------
__device__ float g_mask[(size_t)Bb * Rr * Rr];      // 32 MB
__device__ float g_qkv [(size_t)Bb * Rr * 3 * Dm];  // 24 MB
__device__ float g_h   [(size_t)Bb * Rr * FFd];     // 32 MB
__device__ float g_att [(size_t)Bb * Rr * Dm];      // 8 MB
__device__ float g_tmp [(size_t)Bb * Rr * Dm];      // 8 MB

// ---------------- mask construction ----------------------------------------
__global__ void mask_init_kernel(float* __restrict__ m) {
    int i = blockIdx.x * blockDim.x + threadIdx.x;
    if (i >= Bb * Rr * Rr) return;
    int rc = i % (Rr * Rr);
    m[i] = ((rc / Rr) == (rc % Rr)) ? 0.0f : NEG;
}

__global__ void mask_edges_zero_kernel(float* __restrict__ m,
                                       const int* __restrict__ ei,
                                       const int* __restrict__ keep) {
    int idx = blockIdx.x * blockDim.x + threadIdx.x;
    if (idx >= Bb * Ee) return;
    if (!keep[idx]) return;
    int b = idx / Ee, e = idx % Ee;
    int src = ei[(size_t)b * 2 * Ee + e];
    int dst = ei[(size_t)b * 2 * Ee + Ee + e];
    m[((size_t)b * Rr + src) * Rr + dst] = 0.0f;   // max(NEG, 0) -> 0, race-free
}

__global__ void mask_edges_bias_kernel(float* __restrict__ m,
                                       const int* __restrict__ ei,
                                       const int* __restrict__ rid,
                                       const int* __restrict__ keep,
                                       const float* __restrict__ rb) {
    int idx = blockIdx.x * blockDim.x + threadIdx.x;
    if (idx >= Bb * Ee) return;
    if (!keep[idx]) return;
    int b = idx / Ee, e = idx % Ee;
    int src = ei[(size_t)b * 2 * Ee + e];
    int dst = ei[(size_t)b * 2 * Ee + Ee + e];
    atomicAdd(&m[((size_t)b * Rr + src) * Rr + dst], rb[rid[idx]]);
}

// ---------------- SGEMM: C[M,N] = A[M,K] @ W[N,K]^T + bias, opt. exact GELU -
// 64x64 tile, BK=16, 256 threads, 4x4 per thread.
__global__ void sgemm_nt_kernel(const float* __restrict__ A,
                                const float* __restrict__ W,
                                const float* __restrict__ bias,
                                float* __restrict__ C,
                                int M, int N, int K, int gelu_flag) {
    __shared__ float As[16][64];
    __shared__ float Bs[16][64];
    int tid = threadIdx.x;
    int m0 = blockIdx.y * 64, n0 = blockIdx.x * 64;
    int tm = tid / 16;        // 0..15 -> row group
    int tn = tid % 16;        // 0..15 -> col group
    int lr = tid / 4;         // 0..63 load row
    int lk = (tid % 4) * 4;   // 0,4,8,12

    const float* Ap = A + (size_t)(m0 + lr) * K + lk;
    const float* Wp = W + (size_t)(n0 + lr) * K + lk;

    float acc[4][4];
#pragma unroll
    for (int i = 0; i < 4; i++)
#pragma unroll
        for (int j = 0; j < 4; j++) acc[i][j] = 0.0f;

    for (int k0 = 0; k0 < K; k0 += 16) {
        float4 a4 = *(const float4*)(Ap + k0);
        float4 b4 = *(const float4*)(Wp + k0);
        __syncthreads();
        As[lk + 0][lr] = a4.x; As[lk + 1][lr] = a4.y;
        As[lk + 2][lr] = a4.z; As[lk + 3][lr] = a4.w;
        Bs[lk + 0][lr] = b4.x; Bs[lk + 1][lr] = b4.y;
        Bs[lk + 2][lr] = b4.z; Bs[lk + 3][lr] = b4.w;
        __syncthreads();
#pragma unroll
        for (int kk = 0; kk < 16; kk++) {
            float4 av = *(const float4*)&As[kk][tm * 4];
            float4 bv = *(const float4*)&Bs[kk][tn * 4];
            float a[4] = {av.x, av.y, av.z, av.w};
            float b[4] = {bv.x, bv.y, bv.z, bv.w};
#pragma unroll
            for (int i = 0; i < 4; i++)
#pragma unroll
                for (int j = 0; j < 4; j++) acc[i][j] += a[i] * b[j];
        }
    }

    const float4 bia = *(const float4*)&bias[n0 + tn * 4];
#pragma unroll
    for (int i = 0; i < 4; i++) {
        float4 v;
        v.x = acc[i][0] + bia.x;
        v.y = acc[i][1] + bia.y;
        v.z = acc[i][2] + bia.z;
        v.w = acc[i][3] + bia.w;
        if (gelu_flag) {
            v.x = 0.5f * v.x * (1.0f + erff(v.x * 0.7071067811865475f));
            v.y = 0.5f * v.y * (1.0f + erff(v.y * 0.7071067811865475f));
            v.z = 0.5f * v.z * (1.0f + erff(v.z * 0.7071067811865475f));
            v.w = 0.5f * v.w * (1.0f + erff(v.w * 0.7071067811865475f));
        }
        *(float4*)&C[(size_t)(m0 + tm * 4 + i) * N + n0 + tn * 4] = v;
    }
}

// ---------------- flash attention with graph mask ---------------------------
// grid (R/64, B*H), 256 threads. warp w owns q rows w*8..w*8+7.
__global__ void flash_attn_kernel(const float* __restrict__ qkv,
                                  const float* __restrict__ mask,
                                  float* __restrict__ out) {
    __shared__ float Qs[64][36];
    __shared__ float Ks[64][36];
    __shared__ float Vs[64][36];
    __shared__ float Ps[64][68];

    int bh = blockIdx.y;
    int b = bh >> 3, h = bh & 7;
    int q0 = blockIdx.x * 64;
    int tid = threadIdx.x;
    int w = tid >> 5, lane = tid & 31;
    int r0 = w * 8;
    const float scale = 0.17677669529663687f; // 1/sqrt(32)

    // load Q (scaled)
    {
        int r = tid >> 2;
        int c = (tid & 3) * 8;
        const float* src = qkv + ((size_t)(b * Rr + q0 + r) * (3 * Dm)) + h * HDd + c;
        float4 v0 = *(const float4*)(src);
        float4 v1 = *(const float4*)(src + 4);
        Qs[r][c + 0] = v0.x * scale; Qs[r][c + 1] = v0.y * scale;
        Qs[r][c + 2] = v0.z * scale; Qs[r][c + 3] = v0.w * scale;
        Qs[r][c + 4] = v1.x * scale; Qs[r][c + 5] = v1.y * scale;
        Qs[r][c + 6] = v1.z * scale; Qs[r][c + 7] = v1.w * scale;
    }

    float m_prev[8], l_acc[8], O8[8];
#pragma unroll
    for (int i = 0; i < 8; i++) { m_prev[i] = -1e30f; l_acc[i] = 0.0f; O8[i] = 0.0f; }

    for (int kt = 0; kt < 16; kt++) {
        int k0 = kt * 64;
        {
            int r = tid >> 2;
            int c = (tid & 3) * 8;
            const float* ksrc = qkv + ((size_t)(b * Rr + k0 + r) * (3 * Dm)) + Dm + h * HDd + c;
            const float* vsrc = ksrc + Dm;
            float4 k4a = *(const float4*)(ksrc);
            float4 k4b = *(const float4*)(ksrc + 4);
            float4 v4a = *(const float4*)(vsrc);
            float4 v4b = *(const float4*)(vsrc + 4);
            Ks[r][c + 0] = k4a.x; Ks[r][c + 1] = k4a.y; Ks[r][c + 2] = k4a.z; Ks[r][c + 3] = k4a.w;
            Ks[r][c + 4] = k4b.x; Ks[r][c + 5] = k4b.y; Ks[r][c + 6] = k4b.z; Ks[r][c + 7] = k4b.w;
            Vs[r][c + 0] = v4a.x; Vs[r][c + 1] = v4a.y; Vs[r][c + 2] = v4a.z; Vs[r][c + 3] = v4a.w;
            Vs[r][c + 4] = v4b.x; Vs[r][c + 5] = v4b.y; Vs[r][c + 6] = v4b.z; Vs[r][c + 7] = v4b.w;
        }
        __syncthreads();

        float s[8][2];
#pragma unroll
        for (int i = 0; i < 8; i++) {
            const float* mrow = mask + ((size_t)(b * Rr + q0 + r0 + i)) * Rr + k0;
            s[i][0] = mrow[lane];
            s[i][1] = mrow[lane + 32];
        }
#pragma unroll
        for (int d4 = 0; d4 < 8; d4++) {
            float4 ka = *(const float4*)&Ks[lane][d4 * 4];
            float4 kb = *(const float4*)&Ks[lane + 32][d4 * 4];
#pragma unroll
            for (int i = 0; i < 8; i++) {
                float4 qv = *(const float4*)&Qs[r0 + i][d4 * 4];
                s[i][0] += qv.x * ka.x + qv.y * ka.y + qv.z * ka.z + qv.w * ka.w;
                s[i][1] += qv.x * kb.x + qv.y * kb.y + qv.z * kb.z + qv.w * kb.w;
            }
        }
        // online softmax
#pragma unroll
        for (int i = 0; i < 8; i++) {
            float mt = fmaxf(s[i][0], s[i][1]);
#pragma unroll
            for (int off = 16; off > 0; off >>= 1)
                mt = fmaxf(mt, __shfl_xor_sync(0xffffffffu, mt, off));
            float m_new = fmaxf(m_prev[i], mt);
            float alpha = __expf(m_prev[i] - m_new);
            float p0 = __expf(s[i][0] - m_new);
            float p1 = __expf(s[i][1] - m_new);
            float ps = p0 + p1;
#pragma unroll
            for (int off = 16; off > 0; off >>= 1)
                ps += __shfl_xor_sync(0xffffffffu, ps, off);
            l_acc[i] = l_acc[i] * alpha + ps;
            m_prev[i] = m_new;
            O8[i] *= alpha;
            Ps[r0 + i][lane] = p0;
            Ps[r0 + i][lane + 32] = p1;
        }
        __syncthreads();
        // O += P @ V
#pragma unroll
        for (int c4 = 0; c4 < 16; c4++) {
            float v0 = Vs[c4 * 4 + 0][lane];
            float v1 = Vs[c4 * 4 + 1][lane];
            float v2 = Vs[c4 * 4 + 2][lane];
            float v3 = Vs[c4 * 4 + 3][lane];
#pragma unroll
            for (int i = 0; i < 8; i++) {
                float4 pv = *(const float4*)&Ps[r0 + i][c4 * 4];
                O8[i] += pv.x * v0 + pv.y * v1 + pv.z * v2 + pv.w * v3;
            }
        }
        __syncthreads();
    }

#pragma unroll
    for (int i = 0; i < 8; i++) {
        out[((size_t)(b * Rr + q0 + r0 + i)) * Dm + h * HDd + lane] = O8[i] / l_acc[i];
    }
}

// ---------------- fused residual-add + LayerNorm ----------------------------
__global__ void add_ln_kernel(float* __restrict__ x, const float* __restrict__ d,
                              const float* __restrict__ g, const float* __restrict__ bb) {
    __shared__ float red[8];
    int row = blockIdx.x;
    int tid = threadIdx.x;
    int w = tid >> 5, lane = tid & 31;
    size_t idx = (size_t)row * Dm + tid;
    float v = x[idx] + d[idx];

    float s = v;
#pragma unroll
    for (int off = 16; off > 0; off >>= 1) s += __shfl_xor_sync(0xffffffffu, s, off);
    if (lane == 0) red[w] = s;
    __syncthreads();
    float tot = red[0] + red[1] + red[2] + red[3] + red[4] + red[5] + red[6] + red[7];
    float mu = tot * (1.0f / Dm);
    __syncthreads();

    float dv = v - mu;
    float sq = dv * dv;
#pragma unroll
    for (int off = 16; off > 0; off >>= 1) sq += __shfl_xor_sync(0xffffffffu, sq, off);
    if (lane == 0) red[w] = sq;
    __syncthreads();
    float var = (red[0] + red[1] + red[2] + red[3] + red[4] + red[5] + red[6] + red[7]) * (1.0f / Dm);

    x[idx] = dv * rsqrtf(var + 1e-5f) * g[tid] + bb[tid];
}

// ---------------- launch -----------------------------------------------------
extern "C" void kernel_launch(void* const* d_in, const int* in_sizes, int n_in,
                              void* d_out, int out_size) {
    const float* node = (const float*)d_in[0];
    const int* ei = (const int*)d_in[1];
    const int* rid = (const int*)d_in[2];
    const int* keep = (const int*)d_in[3];
    const float* rb = (const float*)d_in[4];
    const float* Wqkv = (const float*)d_in[5];
    const float* bqkv = (const float*)d_in[6];
    const float* Wo = (const float*)d_in[7];
    const float* bo = (const float*)d_in[8];
    const float* ln1g = (const float*)d_in[9];
    const float* ln1b = (const float*)d_in[10];
    const float* W1 = (const float*)d_in[11];
    const float* b1 = (const float*)d_in[12];
    const float* W2 = (const float*)d_in[13];
    const float* b2 = (const float*)d_in[14];
    const float* ln2g = (const float*)d_in[15];
    const float* ln2b = (const float*)d_in[16];
    float* x = (float*)d_out;

    float *mask, *qkv, *hbuf, *att, *tmp;
    cudaGetSymbolAddress((void**)&mask, g_mask);
    cudaGetSymbolAddress((void**)&qkv, g_qkv);
    cudaGetSymbolAddress((void**)&hbuf, g_h);
    cudaGetSymbolAddress((void**)&att, g_att);
    cudaGetSymbolAddress((void**)&tmp, g_tmp);

    const int M = Bb * Rr; // 8192

    cudaMemcpyAsync(x, node, sizeof(float) * (size_t)M * Dm,
                    cudaMemcpyDeviceToDevice, 0);

    mask_init_kernel<<<(Bb * Rr * Rr + 255) / 256, 256>>>(mask);
    mask_edges_zero_kernel<<<(Bb * Ee + 255) / 256, 256>>>(mask, ei, keep);
    mask_edges_bias_kernel<<<(Bb * Ee + 255) / 256, 256>>>(mask, ei, rid, keep, rb);

    for (int l = 0; l < Ll; l++) {
        // QKV: [8192,256] @ [768,256]^T
        sgemm_nt_kernel<<<dim3(768 / 64, M / 64), 256>>>(
            x, Wqkv + (size_t)l * 3 * Dm * Dm, bqkv + (size_t)l * 3 * Dm,
            qkv, M, 3 * Dm, Dm, 0);
        // attention
        flash_attn_kernel<<<dim3(Rr / 64, Bb * Hh), 256>>>(qkv, mask, att);
        // Wo: [8192,256] @ [256,256]^T
        sgemm_nt_kernel<<<dim3(Dm / 64, M / 64), 256>>>(
            att, Wo + (size_t)l * Dm * Dm, bo + (size_t)l * Dm,
            tmp, M, Dm, Dm, 0);
        add_ln_kernel<<<M, Dm>>>(x, tmp, ln1g + (size_t)l * Dm, ln1b + (size_t)l * Dm);
        // FF1 + GELU: [8192,256] @ [1024,256]^T
        sgemm_nt_kernel<<<dim3(FFd / 64, M / 64), 256>>>(
            x, W1 + (size_t)l * FFd * Dm, b1 + (size_t)l * FFd,
            hbuf, M, FFd, Dm, 1);
        // FF2: [8192,1024] @ [256,1024]^T
        sgemm_nt_kernel<<<dim3(Dm / 64, M / 64), 256>>>(
            hbuf, W2 + (size_t)l * Dm * FFd, b2 + (size_t)l * Dm,
            tmp, M, Dm, FFd, 0);
        add_ln_kernel<<<M, Dm>>>(x, tmp, ln2g + (size_t)l * Dm, ln2b + (size_t)l * Dm);
    }
}

// round 4
// speedup vs baseline: 1.4938x; 1.4938x over previous
#include <cuda_runtime.h>
#include <cuda_bf16.h>
#include <math.h>
#include <stdint.h>

#define Bb 8
#define Rr 1024
#define Dm 256
#define Hh 8
#define Ll 2
#define Ee 32768
#define FFd 1024
#define HDd 32
#define NEG -1000000000.0f

#define Mrows (Bb * Rr) // 8192

// ---------------- scratch (device globals; no allocation allowed) -----------
__device__ float g_mask[(size_t)Bb * Rr * Rr];          // 32 MB
__device__ float g_qkv [(size_t)Mrows * 3 * Dm];        // 24 MB
__device__ float g_tmp [(size_t)Mrows * Dm];            // 8 MB
__device__ __nv_bfloat16 g_xh[(size_t)Mrows * Dm];
__device__ __nv_bfloat16 g_xl[(size_t)Mrows * Dm];
__device__ __nv_bfloat16 g_ah[(size_t)Mrows * Dm];
__device__ __nv_bfloat16 g_al[(size_t)Mrows * Dm];
__device__ __nv_bfloat16 g_hh[(size_t)Mrows * FFd];
__device__ __nv_bfloat16 g_hl[(size_t)Mrows * FFd];
__device__ __nv_bfloat16 g_wqkvh[(size_t)Ll * 3 * Dm * Dm];
__device__ __nv_bfloat16 g_wqkvl[(size_t)Ll * 3 * Dm * Dm];
__device__ __nv_bfloat16 g_woh[(size_t)Ll * Dm * Dm];
__device__ __nv_bfloat16 g_wol[(size_t)Ll * Dm * Dm];
__device__ __nv_bfloat16 g_w1h[(size_t)Ll * FFd * Dm];
__device__ __nv_bfloat16 g_w1l[(size_t)Ll * FFd * Dm];
__device__ __nv_bfloat16 g_w2h[(size_t)Ll * Dm * FFd];
__device__ __nv_bfloat16 g_w2l[(size_t)Ll * Dm * FFd];

// ---------------- small PTX helpers (all plain sm_80-class features) --------
__device__ __forceinline__ uint32_t smem_u32(const void* p) {
    uint32_t a;
    asm("{ .reg .u64 t; cvta.to.shared.u64 t, %1; cvt.u32.u64 %0, t; }" : "=r"(a) : "l"(p));
    return a;
}
__device__ __forceinline__ void cpasync16(uint32_t dst, const void* src) {
    asm volatile("cp.async.ca.shared.global [%0], [%1], 16;" :: "r"(dst), "l"(src) : "memory");
}
__device__ __forceinline__ void cp_commit() {
    asm volatile("cp.async.commit_group;" ::: "memory");
}
template <int N>
__device__ __forceinline__ void cp_wait() {
    asm volatile("cp.async.wait_group %0;" :: "n"(N) : "memory");
}
__device__ __forceinline__ void ldm4(uint32_t* r, uint32_t addr) {
    asm volatile("ldmatrix.sync.aligned.m8n8.x4.shared.b16 {%0,%1,%2,%3}, [%4];"
                 : "=r"(r[0]), "=r"(r[1]), "=r"(r[2]), "=r"(r[3]) : "r"(addr));
}
__device__ __forceinline__ void mma16816(float* c, const uint32_t* a, const uint32_t* b) {
    asm volatile(
        "mma.sync.aligned.m16n8k16.row.col.f32.bf16.bf16.f32 "
        "{%0,%1,%2,%3}, {%4,%5,%6,%7}, {%8,%9}, {%0,%1,%2,%3};"
        : "+f"(c[0]), "+f"(c[1]), "+f"(c[2]), "+f"(c[3])
        : "r"(a[0]), "r"(a[1]), "r"(a[2]), "r"(a[3]), "r"(b[0]), "r"(b[1]));
}

// ================= mask construction =========================================
__global__ void mask_init_kernel(float* __restrict__ m) {
    int i = blockIdx.x * blockDim.x + threadIdx.x;
    if (i >= Bb * Rr * Rr) return;
    int rc = i % (Rr * Rr);
    m[i] = ((rc / Rr) == (rc % Rr)) ? 0.0f : NEG;
}
__global__ void mask_edges_zero_kernel(float* __restrict__ m,
                                       const int* __restrict__ ei,
                                       const int* __restrict__ keep) {
    int idx = blockIdx.x * blockDim.x + threadIdx.x;
    if (idx >= Bb * Ee) return;
    if (!keep[idx]) return;
    int b = idx / Ee, e = idx % Ee;
    int src = ei[(size_t)b * 2 * Ee + e];
    int dst = ei[(size_t)b * 2 * Ee + Ee + e];
    m[((size_t)b * Rr + src) * Rr + dst] = 0.0f;
}
__global__ void mask_edges_bias_kernel(float* __restrict__ m,
                                       const int* __restrict__ ei,
                                       const int* __restrict__ rid,
                                       const int* __restrict__ keep,
                                       const float* __restrict__ rb) {
    int idx = blockIdx.x * blockDim.x + threadIdx.x;
    if (idx >= Bb * Ee) return;
    if (!keep[idx]) return;
    int b = idx / Ee, e = idx % Ee;
    int src = ei[(size_t)b * 2 * Ee + e];
    int dst = ei[(size_t)b * 2 * Ee + Ee + e];
    atomicAdd(&m[((size_t)b * Rr + src) * Rr + dst], rb[rid[idx]]);
}

// ================= fp32 -> bf16 hi/lo split ==================================
__global__ void split_kernel(const float* __restrict__ src,
                             __nv_bfloat16* __restrict__ hi,
                             __nv_bfloat16* __restrict__ lo, int n) {
    int i = blockIdx.x * blockDim.x + threadIdx.x;
    if (i >= n) return;
    float v = src[i];
    __nv_bfloat16 h = __float2bfloat16(v);
    hi[i] = h;
    lo[i] = __float2bfloat16(v - __bfloat162float(h));
}

// ================= split-bf16 HMMA GEMM ======================================
// C[M,N] = (Ah+Al)[M,K] @ (Wh+Wl)[N,K]^T + bias  (drops Al*Wl term)
// CTA tile 128x128, 8 warps (4m x 2n), warp tile 32x64 via mma.m16n8k16.
// K-chunks of 32, double-buffered cp.async.
// smem per stage: 4 matrices (Ah,Al,Wh,Wl) x 128 rows x 40 bf16 (stride pad).
#define SKRB 80          // smem row stride in bytes (40 bf16)
#define MATB (128 * SKRB)    // 10240 bytes per matrix
#define STGB (4 * MATB)      // 40960 bytes per stage
#define GEMM_SMEM (2 * STGB) // 81920

__global__ void __launch_bounds__(256, 1) mma_gemm_kernel(
    const __nv_bfloat16* __restrict__ Ah, const __nv_bfloat16* __restrict__ Al,
    const __nv_bfloat16* __restrict__ Wh, const __nv_bfloat16* __restrict__ Wl,
    const float* __restrict__ bias,
    float* __restrict__ outF,
    __nv_bfloat16* __restrict__ outH, __nv_bfloat16* __restrict__ outL,
    int K, int Nld, int mode) {
    extern __shared__ __align__(16) char smem[];
    uint32_t sb = smem_u32(smem);
    const int tid = threadIdx.x, lane = tid & 31, wid = tid >> 5;
    const int wm = wid & 3, wn = wid >> 2;
    const int m0 = blockIdx.y * 128, n0 = blockIdx.x * 128;

    const __nv_bfloat16* base0 = Ah + (size_t)m0 * K;
    const __nv_bfloat16* base1 = Al + (size_t)m0 * K;
    const __nv_bfloat16* base2 = Wh + (size_t)n0 * K;
    const __nv_bfloat16* base3 = Wl + (size_t)n0 * K;

    float acc[2][8][4];
#pragma unroll
    for (int mt = 0; mt < 2; mt++)
#pragma unroll
        for (int nt = 0; nt < 8; nt++)
#pragma unroll
            for (int j = 0; j < 4; j++) acc[mt][nt][j] = 0.0f;

    const int nsteps = K >> 5;

    // --- stage loader: 4 matrices x 128 rows x 2 chunks(16B) = 1024 tasks / 256 thr
    auto load_stage = [&](int kstep, int buf) {
        int k0 = kstep * 32;
#pragma unroll
        for (int i = 0; i < 4; i++) {
            int task = tid + i * 256;          // 0..1023
            int mat = task >> 8;               // 0..3
            int within = task & 255;           // row*2 + chunk
            int row = within >> 1;
            int ch = within & 1;
            const __nv_bfloat16* g =
                (mat == 0 ? base0 : mat == 1 ? base1 : mat == 2 ? base2 : base3)
                + (size_t)row * K + k0 + ch * 8;
            // wait: 32 bf16 per row = 64B = 4 chunks of 16B, not 2!
            (void)g;
        }
    };
    (void)load_stage;

    // corrected loader: 4 matrices x 128 rows x 4 chunks = 2048 tasks -> 8/thread
#define LOAD_STAGE(kstep, buf)                                                   \
    do {                                                                          \
        int _k0 = (kstep) * 32;                                                   \
        _Pragma("unroll")                                                         \
        for (int _i = 0; _i < 8; _i++) {                                          \
            int _task = tid + _i * 256;                                           \
            int _mat = _task >> 9;                                                \
            int _w = _task & 511;                                                 \
            int _row = _w >> 2;                                                   \
            int _ch = _w & 3;                                                     \
            const __nv_bfloat16* _g =                                             \
                (_mat == 0 ? base0 : _mat == 1 ? base1 : _mat == 2 ? base2 : base3) \
                + (size_t)_row * K + _k0 + _ch * 8;                               \
            uint32_t _d = sb + (buf) * STGB + _mat * MATB + _row * SKRB + _ch * 16; \
            cpasync16(_d, _g);                                                    \
        }                                                                         \
    } while (0)

    LOAD_STAGE(0, 0);
    cp_commit();

    // ldmatrix lane address components
    const int arow = lane & 15;           // A: lanes 0-15 -> m0-15 (k lo), 16-31 -> same rows (k hi)
    const int akb = (lane >> 4) * 16;     // A k byte offset within k16 (0 or 16)
    const int brow = ((lane >> 4) & 1) * 8 + (lane & 7); // B: n row within 16-row pair
    const int bkb = ((lane >> 3) & 1) * 16;              // B k byte offset

    for (int s = 0; s < nsteps; s++) {
        if (s + 1 < nsteps) {
            LOAD_STAGE(s + 1, (s + 1) & 1);
            cp_commit();
            cp_wait<1>();
        } else {
            cp_wait<0>();
        }
        __syncthreads();

        uint32_t stg = sb + (s & 1) * STGB;
#pragma unroll
        for (int ks = 0; ks < 2; ks++) {
            uint32_t aH[2][4], aL[2][4], bH[8][2], bL[8][2];
#pragma unroll
            for (int mt = 0; mt < 2; mt++) {
                uint32_t ra = stg + (wm * 32 + mt * 16 + arow) * SKRB + ks * 32 + akb;
                ldm4(aH[mt], ra);
                ldm4(aL[mt], ra + MATB);
            }
#pragma unroll
            for (int np = 0; np < 4; np++) {
                uint32_t rb = stg + 2 * MATB + (wn * 64 + np * 16 + brow) * SKRB + ks * 32 + bkb;
                uint32_t t[4];
                ldm4(t, rb);
                bH[np * 2][0] = t[0]; bH[np * 2][1] = t[1];
                bH[np * 2 + 1][0] = t[2]; bH[np * 2 + 1][1] = t[3];
                ldm4(t, rb + MATB);
                bL[np * 2][0] = t[0]; bL[np * 2][1] = t[1];
                bL[np * 2 + 1][0] = t[2]; bL[np * 2 + 1][1] = t[3];
            }
#pragma unroll
            for (int mt = 0; mt < 2; mt++)
#pragma unroll
                for (int nt = 0; nt < 8; nt++) {
                    mma16816(acc[mt][nt], aH[mt], bH[nt]);
                    mma16816(acc[mt][nt], aH[mt], bL[nt]);
                    mma16816(acc[mt][nt], aL[mt], bH[nt]);
                }
        }
        __syncthreads();
    }

    // ---- epilogue ----
    const int rbase = m0 + wm * 32 + (lane >> 2);
    const int cbase = n0 + wn * 64 + (lane & 3) * 2;
#pragma unroll
    for (int mt = 0; mt < 2; mt++) {
#pragma unroll
        for (int nt = 0; nt < 8; nt++) {
            int col = cbase + nt * 8;
            float b0 = bias[col], b1 = bias[col + 1];
#pragma unroll
            for (int half = 0; half < 2; half++) {
                int row = rbase + mt * 16 + half * 8;
                float c0 = acc[mt][nt][half * 2 + 0] + b0;
                float c1 = acc[mt][nt][half * 2 + 1] + b1;
                size_t idx = (size_t)row * Nld + col;
                if (mode == 0) {
                    float2 v; v.x = c0; v.y = c1;
                    *(float2*)&outF[idx] = v;
                } else {
                    c0 = 0.5f * c0 * (1.0f + erff(c0 * 0.7071067811865475f));
                    c1 = 0.5f * c1 * (1.0f + erff(c1 * 0.7071067811865475f));
                    __nv_bfloat16 h0 = __float2bfloat16(c0);
                    __nv_bfloat16 h1 = __float2bfloat16(c1);
                    __nv_bfloat162 hp; hp.x = h0; hp.y = h1;
                    __nv_bfloat162 lp;
                    lp.x = __float2bfloat16(c0 - __bfloat162float(h0));
                    lp.y = __float2bfloat16(c1 - __bfloat162float(h1));
                    *(__nv_bfloat162*)&outH[idx] = hp;
                    *(__nv_bfloat162*)&outL[idx] = lp;
                }
            }
        }
    }
}

// ================= flash attention (fp32 SIMT), bf16 hi/lo epilogue ==========
__global__ void flash_attn_kernel(const float* __restrict__ qkv,
                                  const float* __restrict__ mask,
                                  __nv_bfloat16* __restrict__ oh,
                                  __nv_bfloat16* __restrict__ ol) {
    __shared__ float Qs[64][36];
    __shared__ float Ks[64][36];
    __shared__ float Vs[64][36];
    __shared__ float Ps[64][68];

    int bh = blockIdx.y;
    int b = bh >> 3, h = bh & 7;
    int q0 = blockIdx.x * 64;
    int tid = threadIdx.x;
    int w = tid >> 5, lane = tid & 31;
    int r0 = w * 8;
    const float scale = 0.17677669529663687f;

    {
        int r = tid >> 2;
        int c = (tid & 3) * 8;
        const float* src = qkv + ((size_t)(b * Rr + q0 + r) * (3 * Dm)) + h * HDd + c;
        float4 v0 = *(const float4*)(src);
        float4 v1 = *(const float4*)(src + 4);
        Qs[r][c + 0] = v0.x * scale; Qs[r][c + 1] = v0.y * scale;
        Qs[r][c + 2] = v0.z * scale; Qs[r][c + 3] = v0.w * scale;
        Qs[r][c + 4] = v1.x * scale; Qs[r][c + 5] = v1.y * scale;
        Qs[r][c + 6] = v1.z * scale; Qs[r][c + 7] = v1.w * scale;
    }

    float m_prev[8], l_acc[8], O8[8];
#pragma unroll
    for (int i = 0; i < 8; i++) { m_prev[i] = -1e30f; l_acc[i] = 0.0f; O8[i] = 0.0f; }

    for (int kt = 0; kt < 16; kt++) {
        int k0 = kt * 64;
        {
            int r = tid >> 2;
            int c = (tid & 3) * 8;
            const float* ksrc = qkv + ((size_t)(b * Rr + k0 + r) * (3 * Dm)) + Dm + h * HDd + c;
            const float* vsrc = ksrc + Dm;
            float4 k4a = *(const float4*)(ksrc);
            float4 k4b = *(const float4*)(ksrc + 4);
            float4 v4a = *(const float4*)(vsrc);
            float4 v4b = *(const float4*)(vsrc + 4);
            Ks[r][c + 0] = k4a.x; Ks[r][c + 1] = k4a.y; Ks[r][c + 2] = k4a.z; Ks[r][c + 3] = k4a.w;
            Ks[r][c + 4] = k4b.x; Ks[r][c + 5] = k4b.y; Ks[r][c + 6] = k4b.z; Ks[r][c + 7] = k4b.w;
            Vs[r][c + 0] = v4a.x; Vs[r][c + 1] = v4a.y; Vs[r][c + 2] = v4a.z; Vs[r][c + 3] = v4a.w;
            Vs[r][c + 4] = v4b.x; Vs[r][c + 5] = v4b.y; Vs[r][c + 6] = v4b.z; Vs[r][c + 7] = v4b.w;
        }
        __syncthreads();

        float s[8][2];
#pragma unroll
        for (int i = 0; i < 8; i++) {
            const float* mrow = mask + ((size_t)(b * Rr + q0 + r0 + i)) * Rr + k0;
            s[i][0] = mrow[lane];
            s[i][1] = mrow[lane + 32];
        }
#pragma unroll
        for (int d4 = 0; d4 < 8; d4++) {
            float4 ka = *(const float4*)&Ks[lane][d4 * 4];
            float4 kb = *(const float4*)&Ks[lane + 32][d4 * 4];
#pragma unroll
            for (int i = 0; i < 8; i++) {
                float4 qv = *(const float4*)&Qs[r0 + i][d4 * 4];
                s[i][0] += qv.x * ka.x + qv.y * ka.y + qv.z * ka.z + qv.w * ka.w;
                s[i][1] += qv.x * kb.x + qv.y * kb.y + qv.z * kb.z + qv.w * kb.w;
            }
        }
#pragma unroll
        for (int i = 0; i < 8; i++) {
            float mt = fmaxf(s[i][0], s[i][1]);
#pragma unroll
            for (int off = 16; off > 0; off >>= 1)
                mt = fmaxf(mt, __shfl_xor_sync(0xffffffffu, mt, off));
            float m_new = fmaxf(m_prev[i], mt);
            float alpha = __expf(m_prev[i] - m_new);
            float p0 = __expf(s[i][0] - m_new);
            float p1 = __expf(s[i][1] - m_new);
            float ps = p0 + p1;
#pragma unroll
            for (int off = 16; off > 0; off >>= 1)
                ps += __shfl_xor_sync(0xffffffffu, ps, off);
            l_acc[i] = l_acc[i] * alpha + ps;
            m_prev[i] = m_new;
            O8[i] *= alpha;
            Ps[r0 + i][lane] = p0;
            Ps[r0 + i][lane + 32] = p1;
        }
        __syncthreads();
#pragma unroll
        for (int c4 = 0; c4 < 16; c4++) {
            float v0 = Vs[c4 * 4 + 0][lane];
            float v1 = Vs[c4 * 4 + 1][lane];
            float v2 = Vs[c4 * 4 + 2][lane];
            float v3 = Vs[c4 * 4 + 3][lane];
#pragma unroll
            for (int i = 0; i < 8; i++) {
                float4 pv = *(const float4*)&Ps[r0 + i][c4 * 4];
                O8[i] += pv.x * v0 + pv.y * v1 + pv.z * v2 + pv.w * v3;
            }
        }
        __syncthreads();
    }

#pragma unroll
    for (int i = 0; i < 8; i++) {
        float o = O8[i] / l_acc[i];
        size_t idx = ((size_t)(b * Rr + q0 + r0 + i)) * Dm + h * HDd + lane;
        __nv_bfloat16 hb = __float2bfloat16(o);
        oh[idx] = hb;
        ol[idx] = __float2bfloat16(o - __bfloat162float(hb));
    }
}

// ================= fused residual-add + LayerNorm (+ bf16 split out) =========
__global__ void add_ln_kernel(float* __restrict__ x, const float* __restrict__ d,
                              const float* __restrict__ g, const float* __restrict__ bb,
                              __nv_bfloat16* __restrict__ xh, __nv_bfloat16* __restrict__ xl) {
    __shared__ float red[8];
    int row = blockIdx.x;
    int tid = threadIdx.x;
    int w = tid >> 5, lane = tid & 31;
    size_t idx = (size_t)row * Dm + tid;
    float v = x[idx] + d[idx];

    float s = v;
#pragma unroll
    for (int off = 16; off > 0; off >>= 1) s += __shfl_xor_sync(0xffffffffu, s, off);
    if (lane == 0) red[w] = s;
    __syncthreads();
    float mu = (red[0] + red[1] + red[2] + red[3] + red[4] + red[5] + red[6] + red[7]) * (1.0f / Dm);
    __syncthreads();

    float dv = v - mu;
    float sq = dv * dv;
#pragma unroll
    for (int off = 16; off > 0; off >>= 1) sq += __shfl_xor_sync(0xffffffffu, sq, off);
    if (lane == 0) red[w] = sq;
    __syncthreads();
    float var = (red[0] + red[1] + red[2] + red[3] + red[4] + red[5] + red[6] + red[7]) * (1.0f / Dm);

    float y = dv * rsqrtf(var + 1e-5f) * g[tid] + bb[tid];
    x[idx] = y;
    __nv_bfloat16 hb = __float2bfloat16(y);
    xh[idx] = hb;
    xl[idx] = __float2bfloat16(y - __bfloat162float(hb));
}

// ================= launch =====================================================
extern "C" void kernel_launch(void* const* d_in, const int* in_sizes, int n_in,
                              void* d_out, int out_size) {
    const float* node = (const float*)d_in[0];
    const int* ei = (const int*)d_in[1];
    const int* rid = (const int*)d_in[2];
    const int* keep = (const int*)d_in[3];
    const float* rb = (const float*)d_in[4];
    const float* Wqkv = (const float*)d_in[5];
    const float* bqkv = (const float*)d_in[6];
    const float* Wo = (const float*)d_in[7];
    const float* bo = (const float*)d_in[8];
    const float* ln1g = (const float*)d_in[9];
    const float* ln1b = (const float*)d_in[10];
    const float* W1 = (const float*)d_in[11];
    const float* b1 = (const float*)d_in[12];
    const float* W2 = (const float*)d_in[13];
    const float* b2 = (const float*)d_in[14];
    const float* ln2g = (const float*)d_in[15];
    const float* ln2b = (const float*)d_in[16];
    float* x = (float*)d_out;

    float *mask, *qkv, *tmp;
    __nv_bfloat16 *xh, *xl, *ah, *al, *hh, *hl;
    __nv_bfloat16 *wqkvh, *wqkvl, *woh, *wol, *w1h, *w1l, *w2h, *w2l;
    cudaGetSymbolAddress((void**)&mask, g_mask);
    cudaGetSymbolAddress((void**)&qkv, g_qkv);
    cudaGetSymbolAddress((void**)&tmp, g_tmp);
    cudaGetSymbolAddress((void**)&xh, g_xh);
    cudaGetSymbolAddress((void**)&xl, g_xl);
    cudaGetSymbolAddress((void**)&ah, g_ah);
    cudaGetSymbolAddress((void**)&al, g_al);
    cudaGetSymbolAddress((void**)&hh, g_hh);
    cudaGetSymbolAddress((void**)&hl, g_hl);
    cudaGetSymbolAddress((void**)&wqkvh, g_wqkvh);
    cudaGetSymbolAddress((void**)&wqkvl, g_wqkvl);
    cudaGetSymbolAddress((void**)&woh, g_woh);
    cudaGetSymbolAddress((void**)&wol, g_wol);
    cudaGetSymbolAddress((void**)&w1h, g_w1h);
    cudaGetSymbolAddress((void**)&w1l, g_w1l);
    cudaGetSymbolAddress((void**)&w2h, g_w2h);
    cudaGetSymbolAddress((void**)&w2l, g_w2l);

    cudaFuncSetAttribute(mma_gemm_kernel, cudaFuncAttributeMaxDynamicSharedMemorySize, GEMM_SMEM);

    cudaMemcpyAsync(x, node, sizeof(float) * (size_t)Mrows * Dm, cudaMemcpyDeviceToDevice, 0);

    // weight + initial activation splits
    split_kernel<<<(Mrows * Dm + 255) / 256, 256>>>(node, xh, xl, Mrows * Dm);
    split_kernel<<<(Ll * 3 * Dm * Dm + 255) / 256, 256>>>(Wqkv, wqkvh, wqkvl, Ll * 3 * Dm * Dm);
    split_kernel<<<(Ll * Dm * Dm + 255) / 256, 256>>>(Wo, woh, wol, Ll * Dm * Dm);
    split_kernel<<<(Ll * FFd * Dm + 255) / 256, 256>>>(W1, w1h, w1l, Ll * FFd * Dm);
    split_kernel<<<(Ll * Dm * FFd + 255) / 256, 256>>>(W2, w2h, w2l, Ll * Dm * FFd);

    mask_init_kernel<<<(Bb * Rr * Rr + 255) / 256, 256>>>(mask);
    mask_edges_zero_kernel<<<(Bb * Ee + 255) / 256, 256>>>(mask, ei, keep);
    mask_edges_bias_kernel<<<(Bb * Ee + 255) / 256, 256>>>(mask, ei, rid, keep, rb);

    for (int l = 0; l < Ll; l++) {
        // QKV: [8192,768] = x @ Wqkv^T
        mma_gemm_kernel<<<dim3(3 * Dm / 128, Mrows / 128), 256, GEMM_SMEM>>>(
            xh, xl, wqkvh + (size_t)l * 3 * Dm * Dm, wqkvl + (size_t)l * 3 * Dm * Dm,
            bqkv + (size_t)l * 3 * Dm, qkv, nullptr, nullptr, Dm, 3 * Dm, 0);
        // attention -> att hi/lo
        flash_attn_kernel<<<dim3(Rr / 64, Bb * Hh), 256>>>(qkv, mask, ah, al);
        // Wo
        mma_gemm_kernel<<<dim3(Dm / 128, Mrows / 128), 256, GEMM_SMEM>>>(
            ah, al, woh + (size_t)l * Dm * Dm, wol + (size_t)l * Dm * Dm,
            bo + (size_t)l * Dm, tmp, nullptr, nullptr, Dm, Dm, 0);
        add_ln_kernel<<<Mrows, Dm>>>(x, tmp, ln1g + (size_t)l * Dm, ln1b + (size_t)l * Dm, xh, xl);
        // FF1 + GELU -> h hi/lo
        mma_gemm_kernel<<<dim3(FFd / 128, Mrows / 128), 256, GEMM_SMEM>>>(
            xh, xl, w1h + (size_t)l * FFd * Dm, w1l + (size_t)l * FFd * Dm,
            b1 + (size_t)l * FFd, nullptr, hh, hl, Dm, FFd, 1);
        // FF2
        mma_gemm_kernel<<<dim3(Dm / 128, Mrows / 128), 256, GEMM_SMEM>>>(
            hh, hl, w2h + (size_t)l * Dm * FFd, w2l + (size_t)l * Dm * FFd,
            b2 + (size_t)l * Dm, tmp, nullptr, nullptr, FFd, Dm, 0);
        add_ln_kernel<<<Mrows, Dm>>>(x, tmp, ln2g + (size_t)l * Dm, ln2b + (size_t)l * Dm, xh, xl);
    }
}

// round 5
// speedup vs baseline: 2.5265x; 1.6913x over previous
#include <cuda_runtime.h>
#include <cuda_bf16.h>
#include <math.h>
#include <stdint.h>

#define Bb 8
#define Rr 1024
#define Dm 256
#define Hh 8
#define Ll 2
#define Ee 32768
#define FFd 1024
#define HDd 32
#define NEG -1000000000.0f

#define Mrows (Bb * Rr) // 8192
#define QSCALE 0.17677669529663687f

// ---------------- scratch (device globals; no allocation allowed) -----------
__device__ float g_mask[(size_t)Bb * Rr * Rr];          // 32 MB
__device__ float g_tmp [(size_t)Mrows * Dm];            // 8 MB
__device__ __nv_bfloat16 g_qkvh[(size_t)Mrows * 3 * Dm];
__device__ __nv_bfloat16 g_qkvl[(size_t)Mrows * 3 * Dm];
__device__ __nv_bfloat16 g_xh[(size_t)Mrows * Dm];
__device__ __nv_bfloat16 g_xl[(size_t)Mrows * Dm];
__device__ __nv_bfloat16 g_ah[(size_t)Mrows * Dm];
__device__ __nv_bfloat16 g_al[(size_t)Mrows * Dm];
__device__ __nv_bfloat16 g_hh[(size_t)Mrows * FFd];
__device__ __nv_bfloat16 g_hl[(size_t)Mrows * FFd];
__device__ __nv_bfloat16 g_wqkvh[(size_t)Ll * 3 * Dm * Dm];
__device__ __nv_bfloat16 g_wqkvl[(size_t)Ll * 3 * Dm * Dm];
__device__ __nv_bfloat16 g_woh[(size_t)Ll * Dm * Dm];
__device__ __nv_bfloat16 g_wol[(size_t)Ll * Dm * Dm];
__device__ __nv_bfloat16 g_w1h[(size_t)Ll * FFd * Dm];
__device__ __nv_bfloat16 g_w1l[(size_t)Ll * FFd * Dm];
__device__ __nv_bfloat16 g_w2h[(size_t)Ll * Dm * FFd];
__device__ __nv_bfloat16 g_w2l[(size_t)Ll * Dm * FFd];

// ---------------- PTX helpers (plain sm_80-class features only) --------------
__device__ __forceinline__ uint32_t smem_u32(const void* p) {
    uint32_t a;
    asm("{ .reg .u64 t; cvta.to.shared.u64 t, %1; cvt.u32.u64 %0, t; }" : "=r"(a) : "l"(p));
    return a;
}
__device__ __forceinline__ void cpasync16(uint32_t dst, const void* src) {
    asm volatile("cp.async.ca.shared.global [%0], [%1], 16;" :: "r"(dst), "l"(src) : "memory");
}
__device__ __forceinline__ void cp_commit() {
    asm volatile("cp.async.commit_group;" ::: "memory");
}
template <int N>
__device__ __forceinline__ void cp_wait() {
    asm volatile("cp.async.wait_group %0;" :: "n"(N) : "memory");
}
__device__ __forceinline__ void ldm4(uint32_t* r, uint32_t addr) {
    asm volatile("ldmatrix.sync.aligned.m8n8.x4.shared.b16 {%0,%1,%2,%3}, [%4];"
                 : "=r"(r[0]), "=r"(r[1]), "=r"(r[2]), "=r"(r[3]) : "r"(addr));
}
__device__ __forceinline__ void ldm4t(uint32_t* r, uint32_t addr) {
    asm volatile("ldmatrix.sync.aligned.m8n8.x4.trans.shared.b16 {%0,%1,%2,%3}, [%4];"
                 : "=r"(r[0]), "=r"(r[1]), "=r"(r[2]), "=r"(r[3]) : "r"(addr));
}
__device__ __forceinline__ void mma16816(float* c, const uint32_t* a, const uint32_t* b) {
    asm volatile(
        "mma.sync.aligned.m16n8k16.row.col.f32.bf16.bf16.f32 "
        "{%0,%1,%2,%3}, {%4,%5,%6,%7}, {%8,%9}, {%0,%1,%2,%3};"
        : "+f"(c[0]), "+f"(c[1]), "+f"(c[2]), "+f"(c[3])
        : "r"(a[0]), "r"(a[1]), "r"(a[2]), "r"(a[3]), "r"(b[0]), "r"(b[1]));
}
__device__ __forceinline__ uint32_t packbf(float x, float y) {
    __nv_bfloat162 t;
    t.x = __float2bfloat16(x);
    t.y = __float2bfloat16(y);
    return reinterpret_cast<uint32_t&>(t);
}

// ================= mask construction =========================================
__global__ void mask_init_kernel(float* __restrict__ m) {
    int i = blockIdx.x * blockDim.x + threadIdx.x;
    if (i >= Bb * Rr * Rr) return;
    int rc = i % (Rr * Rr);
    m[i] = ((rc / Rr) == (rc % Rr)) ? 0.0f : NEG;
}
__global__ void mask_edges_zero_kernel(float* __restrict__ m,
                                       const int* __restrict__ ei,
                                       const int* __restrict__ keep) {
    int idx = blockIdx.x * blockDim.x + threadIdx.x;
    if (idx >= Bb * Ee) return;
    if (!keep[idx]) return;
    int b = idx / Ee, e = idx % Ee;
    int src = ei[(size_t)b * 2 * Ee + e];
    int dst = ei[(size_t)b * 2 * Ee + Ee + e];
    m[((size_t)b * Rr + src) * Rr + dst] = 0.0f;
}
__global__ void mask_edges_bias_kernel(float* __restrict__ m,
                                       const int* __restrict__ ei,
                                       const int* __restrict__ rid,
                                       const int* __restrict__ keep,
                                       const float* __restrict__ rb) {
    int idx = blockIdx.x * blockDim.x + threadIdx.x;
    if (idx >= Bb * Ee) return;
    if (!keep[idx]) return;
    int b = idx / Ee, e = idx % Ee;
    int src = ei[(size_t)b * 2 * Ee + e];
    int dst = ei[(size_t)b * 2 * Ee + Ee + e];
    atomicAdd(&m[((size_t)b * Rr + src) * Rr + dst], rb[rid[idx]]);
}

// ================= fp32 -> bf16 hi/lo split ==================================
__global__ void split_kernel(const float* __restrict__ src,
                             __nv_bfloat16* __restrict__ hi,
                             __nv_bfloat16* __restrict__ lo, int n) {
    int i = blockIdx.x * blockDim.x + threadIdx.x;
    if (i >= n) return;
    float v = src[i];
    __nv_bfloat16 h = __float2bfloat16(v);
    hi[i] = h;
    lo[i] = __float2bfloat16(v - __bfloat162float(h));
}

// ================= split-bf16 HMMA GEMM ======================================
// C[M,N] = (Ah+Al)[M,K] @ (Wh+Wl)[N,K]^T + bias  (drops Al*Wl term)
// mode 0: fp32 out.  mode 1: GELU + bf16 hi/lo out.  mode 2: bf16 hi/lo out,
//   columns < 256 scaled by QSCALE (QKV projection: pre-scale Q).
#define SKRB 80              // smem row stride bytes (40 bf16)
#define MATB (128 * SKRB)
#define STGB (4 * MATB)
#define GEMM_SMEM (2 * STGB) // 81920

__global__ void __launch_bounds__(256, 1) mma_gemm_kernel(
    const __nv_bfloat16* __restrict__ Ah, const __nv_bfloat16* __restrict__ Al,
    const __nv_bfloat16* __restrict__ Wh, const __nv_bfloat16* __restrict__ Wl,
    const float* __restrict__ bias,
    float* __restrict__ outF,
    __nv_bfloat16* __restrict__ outH, __nv_bfloat16* __restrict__ outL,
    int K, int Nld, int mode) {
    extern __shared__ __align__(16) char smem[];
    uint32_t sb = smem_u32(smem);
    const int tid = threadIdx.x, lane = tid & 31, wid = tid >> 5;
    const int wm = wid & 3, wn = wid >> 2;
    const int m0 = blockIdx.y * 128, n0 = blockIdx.x * 128;

    const __nv_bfloat16* base0 = Ah + (size_t)m0 * K;
    const __nv_bfloat16* base1 = Al + (size_t)m0 * K;
    const __nv_bfloat16* base2 = Wh + (size_t)n0 * K;
    const __nv_bfloat16* base3 = Wl + (size_t)n0 * K;

    float acc[2][8][4];
#pragma unroll
    for (int mt = 0; mt < 2; mt++)
#pragma unroll
        for (int nt = 0; nt < 8; nt++)
#pragma unroll
            for (int j = 0; j < 4; j++) acc[mt][nt][j] = 0.0f;

    const int nsteps = K >> 5;

#define LOAD_STAGE(kstep, buf)                                                   \
    do {                                                                          \
        int _k0 = (kstep) * 32;                                                   \
        _Pragma("unroll")                                                         \
        for (int _i = 0; _i < 8; _i++) {                                          \
            int _task = tid + _i * 256;                                           \
            int _mat = _task >> 9;                                                \
            int _w = _task & 511;                                                 \
            int _row = _w >> 2;                                                   \
            int _ch = _w & 3;                                                     \
            const __nv_bfloat16* _g =                                             \
                (_mat == 0 ? base0 : _mat == 1 ? base1 : _mat == 2 ? base2 : base3) \
                + (size_t)_row * K + _k0 + _ch * 8;                               \
            uint32_t _d = sb + (buf) * STGB + _mat * MATB + _row * SKRB + _ch * 16; \
            cpasync16(_d, _g);                                                    \
        }                                                                         \
    } while (0)

    LOAD_STAGE(0, 0);
    cp_commit();

    const int arow = lane & 15;
    const int akb = (lane >> 4) * 16;
    const int brow = ((lane >> 4) & 1) * 8 + (lane & 7);
    const int bkb = ((lane >> 3) & 1) * 16;

    for (int s = 0; s < nsteps; s++) {
        if (s + 1 < nsteps) {
            LOAD_STAGE(s + 1, (s + 1) & 1);
            cp_commit();
            cp_wait<1>();
        } else {
            cp_wait<0>();
        }
        __syncthreads();

        uint32_t stg = sb + (s & 1) * STGB;
#pragma unroll
        for (int ks = 0; ks < 2; ks++) {
            uint32_t aH[2][4], aL[2][4], bH[8][2], bL[8][2];
#pragma unroll
            for (int mt = 0; mt < 2; mt++) {
                uint32_t ra = stg + (wm * 32 + mt * 16 + arow) * SKRB + ks * 32 + akb;
                ldm4(aH[mt], ra);
                ldm4(aL[mt], ra + MATB);
            }
#pragma unroll
            for (int np = 0; np < 4; np++) {
                uint32_t rb = stg + 2 * MATB + (wn * 64 + np * 16 + brow) * SKRB + ks * 32 + bkb;
                uint32_t t[4];
                ldm4(t, rb);
                bH[np * 2][0] = t[0]; bH[np * 2][1] = t[1];
                bH[np * 2 + 1][0] = t[2]; bH[np * 2 + 1][1] = t[3];
                ldm4(t, rb + MATB);
                bL[np * 2][0] = t[0]; bL[np * 2][1] = t[1];
                bL[np * 2 + 1][0] = t[2]; bL[np * 2 + 1][1] = t[3];
            }
#pragma unroll
            for (int mt = 0; mt < 2; mt++)
#pragma unroll
                for (int nt = 0; nt < 8; nt++) {
                    mma16816(acc[mt][nt], aH[mt], bH[nt]);
                    mma16816(acc[mt][nt], aH[mt], bL[nt]);
                    mma16816(acc[mt][nt], aL[mt], bH[nt]);
                }
        }
        __syncthreads();
    }

    // ---- epilogue ----
    const int rbase = m0 + wm * 32 + (lane >> 2);
    const int cbase = n0 + wn * 64 + (lane & 3) * 2;
#pragma unroll
    for (int mt = 0; mt < 2; mt++) {
#pragma unroll
        for (int nt = 0; nt < 8; nt++) {
            int col = cbase + nt * 8;
            float b0 = bias[col], b1 = bias[col + 1];
#pragma unroll
            for (int half = 0; half < 2; half++) {
                int row = rbase + mt * 16 + half * 8;
                float c0 = acc[mt][nt][half * 2 + 0] + b0;
                float c1 = acc[mt][nt][half * 2 + 1] + b1;
                size_t idx = (size_t)row * Nld + col;
                if (mode == 0) {
                    float2 v; v.x = c0; v.y = c1;
                    *(float2*)&outF[idx] = v;
                } else {
                    if (mode == 1) {
                        c0 = 0.5f * c0 * (1.0f + erff(c0 * 0.7071067811865475f));
                        c1 = 0.5f * c1 * (1.0f + erff(c1 * 0.7071067811865475f));
                    } else if (col < 256) {  // mode 2: pre-scale Q
                        c0 *= QSCALE;
                        c1 *= QSCALE;
                    }
                    __nv_bfloat16 h0 = __float2bfloat16(c0);
                    __nv_bfloat16 h1 = __float2bfloat16(c1);
                    __nv_bfloat162 hp; hp.x = h0; hp.y = h1;
                    __nv_bfloat162 lp;
                    lp.x = __float2bfloat16(c0 - __bfloat162float(h0));
                    lp.y = __float2bfloat16(c1 - __bfloat162float(h1));
                    *(__nv_bfloat162*)&outH[idx] = hp;
                    *(__nv_bfloat162*)&outL[idx] = lp;
                }
            }
        }
    }
}

// ================= tensor-core flash attention ===============================
// Block: 128 q-rows for one (b,h); 8 warps x 16 rows. 64-key tiles, double-
// buffered cp.async. S = QK^T and O += P V via split-bf16 3-product HMMA.
#define AK 80                 // smem row stride bytes
#define AQHo 0
#define AQLo 10240
#define ASTo 20480
#define ASTB 20480            // per stage: Kh 0, Kl 5120, Vh 10240, Vl 15360
#define ATT_SMEM (ASTo + 2 * ASTB) // 61440

__global__ void __launch_bounds__(256, 2) mma_attn_kernel(
    const __nv_bfloat16* __restrict__ qh_g, const __nv_bfloat16* __restrict__ ql_g,
    const float* __restrict__ mask,
    __nv_bfloat16* __restrict__ oh_g, __nv_bfloat16* __restrict__ ol_g) {
    extern __shared__ __align__(16) char smem[];
    uint32_t sb = smem_u32(smem);
    const int tid = threadIdx.x, lane = tid & 31, wid = tid >> 5;
    const int bI = blockIdx.y >> 3, h = blockIdx.y & 7;
    const int q0 = blockIdx.x * 128;
    const int wq = wid * 16;

    // ---- Q tile load: 128 rows x 64B x 2 mats = 1024 16B tasks -> 4/thread
#pragma unroll
    for (int i = 0; i < 4; i++) {
        int task = tid + i * 256;
        int mat = task >> 9, w = task & 511, row = w >> 2, ch = w & 3;
        const __nv_bfloat16* g = (mat ? ql_g : qh_g)
            + ((size_t)(bI * Rr + q0 + row)) * 768 + h * 32 + ch * 8;
        cpasync16(sb + (mat ? AQLo : AQHo) + row * AK + ch * 16, g);
    }
#define LOADKV(kt, buf)                                                          \
    do {                                                                          \
        int _k0 = (kt) * 64;                                                      \
        _Pragma("unroll")                                                         \
        for (int _i = 0; _i < 4; _i++) {                                          \
            int _t = tid + _i * 256;                                              \
            int _mat = _t >> 8, _w = _t & 255, _row = _w >> 2, _ch = _w & 3;      \
            const __nv_bfloat16* _g = ((_mat & 1) ? ql_g : qh_g)                  \
                + ((size_t)(bI * Rr + _k0 + _row)) * 768                          \
                + ((_mat >> 1) ? 512 : 256) + h * 32 + _ch * 8;                   \
            cpasync16(sb + ASTo + (buf) * ASTB + _mat * 5120 + _row * AK + _ch * 16, _g); \
        }                                                                         \
    } while (0)

    LOADKV(0, 0);
    cp_commit();

    const int arow = lane & 15;
    const int akb = (lane >> 4) * 16;
    const int brow = ((lane >> 4) & 1) * 8 + (lane & 7);
    const int bkb = ((lane >> 3) & 1) * 16;

    uint32_t qfh[2][4], qfl[2][4];
    float oacc[4][4];
#pragma unroll
    for (int nt = 0; nt < 4; nt++)
#pragma unroll
        for (int j = 0; j < 4; j++) oacc[nt][j] = 0.0f;
    float mp0 = -1e30f, mp1 = -1e30f, l0 = 0.0f, l1 = 0.0f;

    for (int kt = 0; kt < 16; kt++) {
        if (kt + 1 < 16) {
            LOADKV(kt + 1, (kt + 1) & 1);
            cp_commit();
            cp_wait<1>();
        } else {
            cp_wait<0>();
        }
        __syncthreads();

        if (kt == 0) {
#pragma unroll
            for (int ks = 0; ks < 2; ks++) {
                uint32_t ra = sb + AQHo + (wq + arow) * AK + ks * 32 + akb;
                ldm4(qfh[ks], ra);
                ldm4(qfl[ks], ra + 10240);
            }
        }

        uint32_t stg = sb + ASTo + (kt & 1) * ASTB;

        // ---- S = Q K^T (split 3-product), 16x64 per warp
        float s[8][4];
#pragma unroll
        for (int j = 0; j < 8; j++)
#pragma unroll
            for (int q = 0; q < 4; q++) s[j][q] = 0.0f;
#pragma unroll
        for (int ks = 0; ks < 2; ks++) {
#pragma unroll
            for (int np = 0; np < 4; np++) {
                uint32_t kh[4], kl[4];
                uint32_t rbadr = stg + (np * 16 + brow) * AK + ks * 32 + bkb;
                ldm4(kh, rbadr);
                ldm4(kl, rbadr + 5120);
                mma16816(s[np * 2],     qfh[ks], &kh[0]);
                mma16816(s[np * 2],     qfh[ks], &kl[0]);
                mma16816(s[np * 2],     qfl[ks], &kh[0]);
                mma16816(s[np * 2 + 1], qfh[ks], &kh[2]);
                mma16816(s[np * 2 + 1], qfh[ks], &kl[2]);
                mma16816(s[np * 2 + 1], qfl[ks], &kh[2]);
            }
        }

        // ---- mask add + online softmax (rows r = lane>>2 and r+8)
        const float* mr0 = mask
            + ((size_t)(bI * Rr + q0 + wq + (lane >> 2))) * Rr + kt * 64 + (lane & 3) * 2;
        const float* mr1 = mr0 + (size_t)8 * Rr;
        float mt0 = -1e30f, mt1 = -1e30f;
#pragma unroll
        for (int j = 0; j < 8; j++) {
            float2 a = *(const float2*)(mr0 + j * 8);
            float2 c = *(const float2*)(mr1 + j * 8);
            s[j][0] += a.x; s[j][1] += a.y;
            s[j][2] += c.x; s[j][3] += c.y;
            mt0 = fmaxf(mt0, fmaxf(s[j][0], s[j][1]));
            mt1 = fmaxf(mt1, fmaxf(s[j][2], s[j][3]));
        }
        mt0 = fmaxf(mt0, __shfl_xor_sync(0xffffffffu, mt0, 1));
        mt0 = fmaxf(mt0, __shfl_xor_sync(0xffffffffu, mt0, 2));
        mt1 = fmaxf(mt1, __shfl_xor_sync(0xffffffffu, mt1, 1));
        mt1 = fmaxf(mt1, __shfl_xor_sync(0xffffffffu, mt1, 2));
        float mn0 = fmaxf(mp0, mt0), mn1 = fmaxf(mp1, mt1);
        float al0 = __expf(mp0 - mn0), al1 = __expf(mp1 - mn1);
        mp0 = mn0; mp1 = mn1;
        float ps0 = 0.0f, ps1 = 0.0f;
#pragma unroll
        for (int j = 0; j < 8; j++) {
            s[j][0] = __expf(s[j][0] - mn0);
            s[j][1] = __expf(s[j][1] - mn0);
            s[j][2] = __expf(s[j][2] - mn1);
            s[j][3] = __expf(s[j][3] - mn1);
            ps0 += s[j][0] + s[j][1];
            ps1 += s[j][2] + s[j][3];
        }
        ps0 += __shfl_xor_sync(0xffffffffu, ps0, 1);
        ps0 += __shfl_xor_sync(0xffffffffu, ps0, 2);
        ps1 += __shfl_xor_sync(0xffffffffu, ps1, 1);
        ps1 += __shfl_xor_sync(0xffffffffu, ps1, 2);
        l0 = l0 * al0 + ps0;
        l1 = l1 * al1 + ps1;
#pragma unroll
        for (int nt = 0; nt < 4; nt++) {
            oacc[nt][0] *= al0; oacc[nt][1] *= al0;
            oacc[nt][2] *= al1; oacc[nt][3] *= al1;
        }

        // ---- O += P V (split 3-product); P frags packed straight from s[][]
#pragma unroll
        for (int ks2 = 0; ks2 < 4; ks2++) {
            int j0 = ks2 * 2, j1 = j0 + 1;
            uint32_t pah[4], pal[4];
            {
                float r00 = s[j0][0], r01 = s[j0][1], r02 = s[j0][2], r03 = s[j0][3];
                float r10 = s[j1][0], r11 = s[j1][1], r12 = s[j1][2], r13 = s[j1][3];
                pah[0] = packbf(r00, r01);
                pah[1] = packbf(r02, r03);
                pah[2] = packbf(r10, r11);
                pah[3] = packbf(r12, r13);
                __nv_bfloat162 t;
                t = reinterpret_cast<__nv_bfloat162&>(pah[0]);
                pal[0] = packbf(r00 - __bfloat162float(t.x), r01 - __bfloat162float(t.y));
                t = reinterpret_cast<__nv_bfloat162&>(pah[1]);
                pal[1] = packbf(r02 - __bfloat162float(t.x), r03 - __bfloat162float(t.y));
                t = reinterpret_cast<__nv_bfloat162&>(pah[2]);
                pal[2] = packbf(r10 - __bfloat162float(t.x), r11 - __bfloat162float(t.y));
                t = reinterpret_cast<__nv_bfloat162&>(pah[3]);
                pal[3] = packbf(r12 - __bfloat162float(t.x), r13 - __bfloat162float(t.y));
            }
            uint32_t vrow = stg + 10240
                + (ks2 * 16 + (lane & 7) + 8 * ((lane >> 3) & 1)) * AK
                + ((lane >> 4) & 1) * 16;
#pragma unroll
            for (int nb = 0; nb < 2; nb++) {
                uint32_t vh[4], vl[4];
                ldm4t(vh, vrow + nb * 32);
                ldm4t(vl, vrow + nb * 32 + 5120);
                mma16816(oacc[nb * 2],     pah, &vh[0]);
                mma16816(oacc[nb * 2],     pah, &vl[0]);
                mma16816(oacc[nb * 2],     pal, &vh[0]);
                mma16816(oacc[nb * 2 + 1], pah, &vh[2]);
                mma16816(oacc[nb * 2 + 1], pah, &vl[2]);
                mma16816(oacc[nb * 2 + 1], pal, &vh[2]);
            }
        }
        __syncthreads();
    }

    // ---- epilogue: normalize, bf16 hi/lo out -----------------------------
    float i0 = 1.0f / l0, i1 = 1.0f / l1;
    size_t row0 = (size_t)(bI * Rr + q0 + wq + (lane >> 2));
#pragma unroll
    for (int nt = 0; nt < 4; nt++) {
        int col = h * 32 + nt * 8 + (lane & 3) * 2;
        float c0 = oacc[nt][0] * i0, c1 = oacc[nt][1] * i0;
        float c2 = oacc[nt][2] * i1, c3 = oacc[nt][3] * i1;
        size_t idx0 = row0 * Dm + col;
        size_t idx1 = (row0 + 8) * Dm + col;
        uint32_t h0 = packbf(c0, c1), h1 = packbf(c2, c3);
        __nv_bfloat162 t0 = reinterpret_cast<__nv_bfloat162&>(h0);
        __nv_bfloat162 t1 = reinterpret_cast<__nv_bfloat162&>(h1);
        *(uint32_t*)&oh_g[idx0] = h0;
        *(uint32_t*)&oh_g[idx1] = h1;
        *(uint32_t*)&ol_g[idx0] =
            packbf(c0 - __bfloat162float(t0.x), c1 - __bfloat162float(t0.y));
        *(uint32_t*)&ol_g[idx1] =
            packbf(c2 - __bfloat162float(t1.x), c3 - __bfloat162float(t1.y));
    }
}

// ================= fused residual-add + LayerNorm (+ bf16 split out) =========
__global__ void add_ln_kernel(float* __restrict__ x, const float* __restrict__ d,
                              const float* __restrict__ g, const float* __restrict__ bb,
                              __nv_bfloat16* __restrict__ xh, __nv_bfloat16* __restrict__ xl) {
    __shared__ float red[8];
    int row = blockIdx.x;
    int tid = threadIdx.x;
    int w = tid >> 5, lane = tid & 31;
    size_t idx = (size_t)row * Dm + tid;
    float v = x[idx] + d[idx];

    float s = v;
#pragma unroll
    for (int off = 16; off > 0; off >>= 1) s += __shfl_xor_sync(0xffffffffu, s, off);
    if (lane == 0) red[w] = s;
    __syncthreads();
    float mu = (red[0] + red[1] + red[2] + red[3] + red[4] + red[5] + red[6] + red[7]) * (1.0f / Dm);
    __syncthreads();

    float dv = v - mu;
    float sq = dv * dv;
#pragma unroll
    for (int off = 16; off > 0; off >>= 1) sq += __shfl_xor_sync(0xffffffffu, sq, off);
    if (lane == 0) red[w] = sq;
    __syncthreads();
    float var = (red[0] + red[1] + red[2] + red[3] + red[4] + red[5] + red[6] + red[7]) * (1.0f / Dm);

    float y = dv * rsqrtf(var + 1e-5f) * g[tid] + bb[tid];
    x[idx] = y;
    __nv_bfloat16 hb = __float2bfloat16(y);
    xh[idx] = hb;
    xl[idx] = __float2bfloat16(y - __bfloat162float(hb));
}

// ================= launch =====================================================
extern "C" void kernel_launch(void* const* d_in, const int* in_sizes, int n_in,
                              void* d_out, int out_size) {
    const float* node = (const float*)d_in[0];
    const int* ei = (const int*)d_in[1];
    const int* rid = (const int*)d_in[2];
    const int* keep = (const int*)d_in[3];
    const float* rb = (const float*)d_in[4];
    const float* Wqkv = (const float*)d_in[5];
    const float* bqkv = (const float*)d_in[6];
    const float* Wo = (const float*)d_in[7];
    const float* bo = (const float*)d_in[8];
    const float* ln1g = (const float*)d_in[9];
    const float* ln1b = (const float*)d_in[10];
    const float* W1 = (const float*)d_in[11];
    const float* b1 = (const float*)d_in[12];
    const float* W2 = (const float*)d_in[13];
    const float* b2 = (const float*)d_in[14];
    const float* ln2g = (const float*)d_in[15];
    const float* ln2b = (const float*)d_in[16];
    float* x = (float*)d_out;

    float *mask, *tmp;
    __nv_bfloat16 *qkvh, *qkvl, *xh, *xl, *ah, *al, *hh, *hl;
    __nv_bfloat16 *wqkvh, *wqkvl, *woh, *wol, *w1h, *w1l, *w2h, *w2l;
    cudaGetSymbolAddress((void**)&mask, g_mask);
    cudaGetSymbolAddress((void**)&tmp, g_tmp);
    cudaGetSymbolAddress((void**)&qkvh, g_qkvh);
    cudaGetSymbolAddress((void**)&qkvl, g_qkvl);
    cudaGetSymbolAddress((void**)&xh, g_xh);
    cudaGetSymbolAddress((void**)&xl, g_xl);
    cudaGetSymbolAddress((void**)&ah, g_ah);
    cudaGetSymbolAddress((void**)&al, g_al);
    cudaGetSymbolAddress((void**)&hh, g_hh);
    cudaGetSymbolAddress((void**)&hl, g_hl);
    cudaGetSymbolAddress((void**)&wqkvh, g_wqkvh);
    cudaGetSymbolAddress((void**)&wqkvl, g_wqkvl);
    cudaGetSymbolAddress((void**)&woh, g_woh);
    cudaGetSymbolAddress((void**)&wol, g_wol);
    cudaGetSymbolAddress((void**)&w1h, g_w1h);
    cudaGetSymbolAddress((void**)&w1l, g_w1l);
    cudaGetSymbolAddress((void**)&w2h, g_w2h);
    cudaGetSymbolAddress((void**)&w2l, g_w2l);

    cudaFuncSetAttribute(mma_gemm_kernel, cudaFuncAttributeMaxDynamicSharedMemorySize, GEMM_SMEM);
    cudaFuncSetAttribute(mma_attn_kernel, cudaFuncAttributeMaxDynamicSharedMemorySize, ATT_SMEM);

    cudaMemcpyAsync(x, node, sizeof(float) * (size_t)Mrows * Dm, cudaMemcpyDeviceToDevice, 0);

    split_kernel<<<(Mrows * Dm + 255) / 256, 256>>>(node, xh, xl, Mrows * Dm);
    split_kernel<<<(Ll * 3 * Dm * Dm + 255) / 256, 256>>>(Wqkv, wqkvh, wqkvl, Ll * 3 * Dm * Dm);
    split_kernel<<<(Ll * Dm * Dm + 255) / 256, 256>>>(Wo, woh, wol, Ll * Dm * Dm);
    split_kernel<<<(Ll * FFd * Dm + 255) / 256, 256>>>(W1, w1h, w1l, Ll * FFd * Dm);
    split_kernel<<<(Ll * Dm * FFd + 255) / 256, 256>>>(W2, w2h, w2l, Ll * Dm * FFd);

    mask_init_kernel<<<(Bb * Rr * Rr + 255) / 256, 256>>>(mask);
    mask_edges_zero_kernel<<<(Bb * Ee + 255) / 256, 256>>>(mask, ei, keep);
    mask_edges_bias_kernel<<<(Bb * Ee + 255) / 256, 256>>>(mask, ei, rid, keep, rb);

    for (int l = 0; l < Ll; l++) {
        // QKV projection -> bf16 hi/lo, Q pre-scaled
        mma_gemm_kernel<<<dim3(3 * Dm / 128, Mrows / 128), 256, GEMM_SMEM>>>(
            xh, xl, wqkvh + (size_t)l * 3 * Dm * Dm, wqkvl + (size_t)l * 3 * Dm * Dm,
            bqkv + (size_t)l * 3 * Dm, nullptr, qkvh, qkvl, Dm, 3 * Dm, 2);
        // tensor-core flash attention -> att hi/lo
        mma_attn_kernel<<<dim3(Rr / 128, Bb * Hh), 256, ATT_SMEM>>>(qkvh, qkvl, mask, ah, al);
        // Wo
        mma_gemm_kernel<<<dim3(Dm / 128, Mrows / 128), 256, GEMM_SMEM>>>(
            ah, al, woh + (size_t)l * Dm * Dm, wol + (size_t)l * Dm * Dm,
            bo + (size_t)l * Dm, tmp, nullptr, nullptr, Dm, Dm, 0);
        add_ln_kernel<<<Mrows, Dm>>>(x, tmp, ln1g + (size_t)l * Dm, ln1b + (size_t)l * Dm, xh, xl);
        // FF1 + GELU -> h hi/lo
        mma_gemm_kernel<<<dim3(FFd / 128, Mrows / 128), 256, GEMM_SMEM>>>(
            xh, xl, w1h + (size_t)l * FFd * Dm, w1l + (size_t)l * FFd * Dm,
            b1 + (size_t)l * FFd, nullptr, hh, hl, Dm, FFd, 1);
        // FF2
        mma_gemm_kernel<<<dim3(Dm / 128, Mrows / 128), 256, GEMM_SMEM>>>(
            hh, hl, w2h + (size_t)l * Dm * FFd, w2l + (size_t)l * Dm * FFd,
            b2 + (size_t)l * Dm, tmp, nullptr, nullptr, FFd, Dm, 0);
        add_ln_kernel<<<Mrows, Dm>>>(x, tmp, ln2g + (size_t)l * Dm, ln2b + (size_t)l * Dm, xh, xl);
    }
}